// round 2
// baseline (speedup 1.0000x reference)
#include <cuda_runtime.h>

#define PP 32768
#define LL 16
#define KK 8
#define HH 128
#define NROWS 64
#define NTHREADS 256

// Full h buffer for all L*P nodes (pred holds GLOBAL indices). 256 MiB static.
__device__ float g_h[(long long)LL * PP * HH];

__device__ __forceinline__ float lrelu(float x) { return x > 0.0f ? x : 0.1f * x; }
__device__ __forceinline__ float relu_(float x) { return x > 0.0f ? x : 0.0f; }

// ---------------------------------------------------------------------------
// h[0:P] = mlp2(delay, pi):  t1 = lrelu(delay*w1+b1) (64), h = t1@w2 + b2 (128)
// ---------------------------------------------------------------------------
__global__ void __launch_bounds__(NTHREADS, 1)
k_init(const float* __restrict__ delay,
       const float* __restrict__ w1, const float* __restrict__ b1,
       const float* __restrict__ w2, const float* __restrict__ b2)
{
    extern __shared__ float smem[];
    float* s_t1 = smem;            // 64*64
    float* s_w2 = s_t1 + 64 * 64;  // 64*128
    float* s_b2 = s_w2 + 64 * 128; // 128

    const int tid  = threadIdx.x;
    const int row0 = blockIdx.x * NROWS;

    for (int i = tid; i < (64 * 128) / 4; i += NTHREADS)
        ((float4*)s_w2)[i] = ((const float4*)w2)[i];
    for (int i = tid; i < 128; i += NTHREADS) s_b2[i] = b2[i];
    for (int i = tid; i < 64 * 64; i += NTHREADS) {
        int r = i >> 6, c = i & 63;
        s_t1[i] = lrelu(delay[row0 + r] * w1[c] + b1[c]);
    }
    __syncthreads();

    const int w = tid >> 5, l = tid & 31;
    const int r0 = w * 8, c0 = l * 4;
    float acc[8][4];
#pragma unroll
    for (int r = 0; r < 8; r++)
#pragma unroll
        for (int c = 0; c < 4; c++) acc[r][c] = 0.0f;

#pragma unroll 4
    for (int k = 0; k < 64; k += 2) {
        float4 w0  = *(const float4*)(s_w2 + k * 128 + c0);
        float4 w1v = *(const float4*)(s_w2 + (k + 1) * 128 + c0);
#pragma unroll
        for (int r = 0; r < 8; r++) {
            float2 a = *(const float2*)(s_t1 + (r0 + r) * 64 + k);
            acc[r][0] = fmaf(a.x, w0.x, acc[r][0]); acc[r][0] = fmaf(a.y, w1v.x, acc[r][0]);
            acc[r][1] = fmaf(a.x, w0.y, acc[r][1]); acc[r][1] = fmaf(a.y, w1v.y, acc[r][1]);
            acc[r][2] = fmaf(a.x, w0.z, acc[r][2]); acc[r][2] = fmaf(a.y, w1v.z, acc[r][2]);
            acc[r][3] = fmaf(a.x, w0.w, acc[r][3]); acc[r][3] = fmaf(a.y, w1v.w, acc[r][3]);
        }
    }
#pragma unroll
    for (int r = 0; r < 8; r++) {
        float4 o;
        o.x = acc[r][0] + s_b2[c0 + 0];
        o.y = acc[r][1] + s_b2[c0 + 1];
        o.z = acc[r][2] + s_b2[c0 + 2];
        o.w = acc[r][3] + s_b2[c0 + 3];
        *(float4*)(g_h + (long long)(row0 + r0 + r) * HH + c0) = o;
    }
}

// ---------------------------------------------------------------------------
// Layer i (i=1..15):
//   neigh = mean_k h[pred[r][k]]                          (gather, 64x128 tile)
//   t = [ lrelu(neigh@ne_w1+ne_b1) | lrelu(feat@sf_w1+sf_b1) ]   (64x128)
//   hn = t @ [ne_w2; sf_w2] + (ne_b2+sf_b2)               (64x128)
//   hn = is_po ? hn : relu(hn);   store to g_h[lo+row]
// ---------------------------------------------------------------------------
__global__ void __launch_bounds__(NTHREADS, 1)
k_layer(int lo,
        const int*   __restrict__ pred,   // slice for this layer: PP*KK
        const float* __restrict__ feat,   // full N*32
        const float* __restrict__ ne_w1, const float* __restrict__ ne_b1,
        const float* __restrict__ ne_w2, const float* __restrict__ ne_b2,
        const float* __restrict__ sf_w1, const float* __restrict__ sf_b1,
        const float* __restrict__ sf_w2, const float* __restrict__ sf_b2,
        const int*   __restrict__ is_po)
{
    extern __shared__ float smem[];
    float* s_nt   = smem;                 // 64*128 = 8192   (neigh, then t)
    float* s_w1ne = s_nt + 8192;          // 128*64 = 8192
    float* s_w1sf = s_w1ne + 8192;        // 32*64  = 2048
    float* s_w2   = s_w1sf + 2048;        // 128*128= 16384  (stacked ne_w2; sf_w2)
    float* s_ft   = s_w2 + 16384;         // 64*32  = 2048
    float* s_b1   = s_ft + 2048;          // 128
    float* s_b2   = s_b1 + 128;           // 128
    int*   s_pred = (int*)(s_b2 + 128);   // 512
    int*   s_po   = s_pred + 512;         // 64

    const int tid  = threadIdx.x;
    const int row0 = blockIdx.x * NROWS;

    // ---- cooperative preload ----
    for (int i = tid; i < 2048; i += NTHREADS)
        ((float4*)s_w1ne)[i] = ((const float4*)ne_w1)[i];
    for (int i = tid; i < 512; i += NTHREADS)
        ((float4*)s_w1sf)[i] = ((const float4*)sf_w1)[i];
    for (int i = tid; i < 4096; i += NTHREADS) {
        int j = i >> 5, c4 = i & 31;
        const float4* src = (j < 64) ? ((const float4*)(ne_w2 + j * 128) + c4)
                                     : ((const float4*)(sf_w2 + (j - 64) * 128) + c4);
        ((float4*)s_w2)[i] = *src;
    }
    for (int i = tid; i < 512; i += NTHREADS) {
        int r = i >> 3, c4 = i & 7;
        ((float4*)s_ft)[i] = *((const float4*)(feat + (long long)(lo + row0 + r) * 32) + c4);
    }
    for (int i = tid; i < 512; i += NTHREADS)
        s_pred[i] = pred[(row0 + (i >> 3)) * KK + (i & 7)];
    for (int i = tid; i < 64; i += NTHREADS)
        s_po[i] = is_po[lo + row0 + i];
    for (int i = tid; i < 128; i += NTHREADS) {
        s_b1[i] = (i < 64) ? ne_b1[i] : sf_b1[i - 64];
        s_b2[i] = ne_b2[i] + sf_b2[i];
    }
    __syncthreads();

    // ---- gather mean of 8 predecessor rows (coalesced: warp = one h row) ----
#pragma unroll
    for (int j = 0; j < 8; j++) {
        int task = tid + j * NTHREADS;
        int r = task >> 5, c4 = task & 31;
        const int* pr = s_pred + r * 8;
        float x = 0.f, y = 0.f, z = 0.f, ww = 0.f;
#pragma unroll
        for (int k = 0; k < 8; k++) {
            const float4 v = *((const float4*)(g_h + (long long)pr[k] * HH) + c4);
            x += v.x; y += v.y; z += v.z; ww += v.w;
        }
        *((float4*)(s_nt + r * 128) + c4) =
            make_float4(x * 0.125f, y * 0.125f, z * 0.125f, ww * 0.125f);
    }
    __syncthreads();

    const int w = tid >> 5, l = tid & 31;
    const int r0 = w * 8;
    const int cA = l * 2;

    // ---- stage 1: ne path (k=128 over neigh) + sf path (k=32 over feat) ----
    float accA[8][2], accB[8][2];
#pragma unroll
    for (int r = 0; r < 8; r++) { accA[r][0] = accA[r][1] = accB[r][0] = accB[r][1] = 0.f; }

#pragma unroll 4
    for (int k = 0; k < 128; k += 2) {
        float2 w0  = *(const float2*)(s_w1ne + k * 64 + cA);
        float2 w1v = *(const float2*)(s_w1ne + (k + 1) * 64 + cA);
#pragma unroll
        for (int r = 0; r < 8; r++) {
            float2 a = *(const float2*)(s_nt + (r0 + r) * 128 + k);
            accA[r][0] = fmaf(a.x, w0.x, accA[r][0]); accA[r][0] = fmaf(a.y, w1v.x, accA[r][0]);
            accA[r][1] = fmaf(a.x, w0.y, accA[r][1]); accA[r][1] = fmaf(a.y, w1v.y, accA[r][1]);
        }
    }
#pragma unroll
    for (int k = 0; k < 32; k += 2) {
        float2 w0  = *(const float2*)(s_w1sf + k * 64 + cA);
        float2 w1v = *(const float2*)(s_w1sf + (k + 1) * 64 + cA);
#pragma unroll
        for (int r = 0; r < 8; r++) {
            float2 a = *(const float2*)(s_ft + (r0 + r) * 32 + k);
            accB[r][0] = fmaf(a.x, w0.x, accB[r][0]); accB[r][0] = fmaf(a.y, w1v.x, accB[r][0]);
            accB[r][1] = fmaf(a.x, w0.y, accB[r][1]); accB[r][1] = fmaf(a.y, w1v.y, accB[r][1]);
        }
    }
    __syncthreads();   // everyone done reading neigh from s_nt

#pragma unroll
    for (int r = 0; r < 8; r++) {
        float* t = s_nt + (r0 + r) * 128;
        t[cA]          = lrelu(accA[r][0] + s_b1[cA]);
        t[cA + 1]      = lrelu(accA[r][1] + s_b1[cA + 1]);
        t[64 + cA]     = lrelu(accB[r][0] + s_b1[64 + cA]);
        t[64 + cA + 1] = lrelu(accB[r][1] + s_b1[64 + cA + 1]);
    }
    __syncthreads();

    // ---- stage 2: t (64x128) @ stacked w2 (128x128) ----
    const int c0 = l * 4;
    float acc[8][4];
#pragma unroll
    for (int r = 0; r < 8; r++) { acc[r][0] = acc[r][1] = acc[r][2] = acc[r][3] = 0.f; }
#pragma unroll 4
    for (int k = 0; k < 128; k += 2) {
        float4 w0  = *(const float4*)(s_w2 + k * 128 + c0);
        float4 w1v = *(const float4*)(s_w2 + (k + 1) * 128 + c0);
#pragma unroll
        for (int r = 0; r < 8; r++) {
            float2 a = *(const float2*)(s_nt + (r0 + r) * 128 + k);
            acc[r][0] = fmaf(a.x, w0.x, acc[r][0]); acc[r][0] = fmaf(a.y, w1v.x, acc[r][0]);
            acc[r][1] = fmaf(a.x, w0.y, acc[r][1]); acc[r][1] = fmaf(a.y, w1v.y, acc[r][1]);
            acc[r][2] = fmaf(a.x, w0.z, acc[r][2]); acc[r][2] = fmaf(a.y, w1v.z, acc[r][2]);
            acc[r][3] = fmaf(a.x, w0.w, acc[r][3]); acc[r][3] = fmaf(a.y, w1v.w, acc[r][3]);
        }
    }
#pragma unroll
    for (int r = 0; r < 8; r++) {
        float4 o;
        o.x = acc[r][0] + s_b2[c0 + 0];
        o.y = acc[r][1] + s_b2[c0 + 1];
        o.z = acc[r][2] + s_b2[c0 + 2];
        o.w = acc[r][3] + s_b2[c0 + 3];
        if (!s_po[r0 + r]) { o.x = relu_(o.x); o.y = relu_(o.y); o.z = relu_(o.z); o.w = relu_(o.w); }
        *(float4*)(g_h + (long long)(lo + row0 + r0 + r) * HH + c0) = o;
    }
}

// ---------------------------------------------------------------------------
// Final head: h_glob = mlp2(PO_feat, gl); out = mlp2([h_gnn | h_glob], out)
// ---------------------------------------------------------------------------
__global__ void __launch_bounds__(NTHREADS, 1)
k_final(const float* __restrict__ PO,
        const float* __restrict__ gl_w1, const float* __restrict__ gl_b1,
        const float* __restrict__ gl_w2, const float* __restrict__ gl_b2,
        const float* __restrict__ out_w1, const float* __restrict__ out_b1,
        const float* __restrict__ out_w2, const float* __restrict__ out_b2,
        float* __restrict__ out)
{
    extern __shared__ float smem[];
    float* s_x   = smem;             // 64*256 = 16384  [h_gnn | h_glob]
    float* s_w   = s_x + 16384;      // 64*128 = 8192   staging (gl_w2, then out_w1 tiles)
    float* s_t   = s_w + 8192;       // 64*132 = 8448   (pitch 132 for reduce)
    float* s_g1  = s_t + 8448;       // 64*64  = 4096
    float* s_gb2 = s_g1 + 4096;      // 128
    float* s_ob1 = s_gb2 + 128;      // 128
    float* s_ow2 = s_ob1 + 128;      // 128

    const int tid  = threadIdx.x;
    const int row0 = blockIdx.x * NROWS;
    const long long gnn0 = (long long)(LL - 1) * PP * HH;

    for (int i = tid; i < 2048; i += NTHREADS)
        ((float4*)s_w)[i] = ((const float4*)gl_w2)[i];
    for (int i = tid; i < 128; i += NTHREADS) {
        s_gb2[i] = gl_b2[i];
        s_ob1[i] = out_b1[i];
        s_ow2[i] = out_w2[i];
    }
    for (int i = tid; i < 64 * 64; i += NTHREADS) {
        int r = i >> 6, c = i & 63;
        s_g1[i] = lrelu(PO[row0 + r] * gl_w1[c] + gl_b1[c]);
    }
    for (int i = tid; i < 2048; i += NTHREADS) {
        int r = i >> 5, c4 = i & 31;
        float4 v = *((const float4*)(g_h + gnn0 + (long long)(row0 + r) * HH) + c4);
        *((float4*)(s_x + r * 256) + c4) = v;
    }
    __syncthreads();

    const int w = tid >> 5, l = tid & 31;
    const int r0 = w * 8, c0 = l * 4;

    // h_glob = lrelu(...)@gl_w2 + gl_b2  -> s_x[:,128:]
    {
        float acc[8][4];
#pragma unroll
        for (int r = 0; r < 8; r++) { acc[r][0] = acc[r][1] = acc[r][2] = acc[r][3] = 0.f; }
#pragma unroll 4
        for (int k = 0; k < 64; k += 2) {
            float4 w0  = *(const float4*)(s_w + k * 128 + c0);
            float4 w1v = *(const float4*)(s_w + (k + 1) * 128 + c0);
#pragma unroll
            for (int r = 0; r < 8; r++) {
                float2 a = *(const float2*)(s_g1 + (r0 + r) * 64 + k);
                acc[r][0] = fmaf(a.x, w0.x, acc[r][0]); acc[r][0] = fmaf(a.y, w1v.x, acc[r][0]);
                acc[r][1] = fmaf(a.x, w0.y, acc[r][1]); acc[r][1] = fmaf(a.y, w1v.y, acc[r][1]);
                acc[r][2] = fmaf(a.x, w0.z, acc[r][2]); acc[r][2] = fmaf(a.y, w1v.z, acc[r][2]);
                acc[r][3] = fmaf(a.x, w0.w, acc[r][3]); acc[r][3] = fmaf(a.y, w1v.w, acc[r][3]);
            }
        }
#pragma unroll
        for (int r = 0; r < 8; r++) {
            float4 o;
            o.x = acc[r][0] + s_gb2[c0 + 0];
            o.y = acc[r][1] + s_gb2[c0 + 1];
            o.z = acc[r][2] + s_gb2[c0 + 2];
            o.w = acc[r][3] + s_gb2[c0 + 3];
            *(float4*)(s_x + (r0 + r) * 256 + 128 + c0) = o;
        }
    }

    // t = lrelu(x @ out_w1 + out_b1), out_w1 staged in 4 k-tiles of 64
    float acc[8][4];
#pragma unroll
    for (int r = 0; r < 8; r++) { acc[r][0] = acc[r][1] = acc[r][2] = acc[r][3] = 0.f; }
    for (int kt = 0; kt < 4; kt++) {
        __syncthreads();
        const float4* src = (const float4*)(out_w1 + kt * 64 * 128);
        for (int i = tid; i < 2048; i += NTHREADS) ((float4*)s_w)[i] = src[i];
        __syncthreads();
#pragma unroll 4
        for (int k = 0; k < 64; k += 2) {
            float4 w0  = *(const float4*)(s_w + k * 128 + c0);
            float4 w1v = *(const float4*)(s_w + (k + 1) * 128 + c0);
#pragma unroll
            for (int r = 0; r < 8; r++) {
                float2 a = *(const float2*)(s_x + (r0 + r) * 256 + kt * 64 + k);
                acc[r][0] = fmaf(a.x, w0.x, acc[r][0]); acc[r][0] = fmaf(a.y, w1v.x, acc[r][0]);
                acc[r][1] = fmaf(a.x, w0.y, acc[r][1]); acc[r][1] = fmaf(a.y, w1v.y, acc[r][1]);
                acc[r][2] = fmaf(a.x, w0.z, acc[r][2]); acc[r][2] = fmaf(a.y, w1v.z, acc[r][2]);
                acc[r][3] = fmaf(a.x, w0.w, acc[r][3]); acc[r][3] = fmaf(a.y, w1v.w, acc[r][3]);
            }
        }
    }
#pragma unroll
    for (int r = 0; r < 8; r++) {
        float* t = s_t + (r0 + r) * 132;
        t[c0 + 0] = lrelu(acc[r][0] + s_ob1[c0 + 0]);
        t[c0 + 1] = lrelu(acc[r][1] + s_ob1[c0 + 1]);
        t[c0 + 2] = lrelu(acc[r][2] + s_ob1[c0 + 2]);
        t[c0 + 3] = lrelu(acc[r][3] + s_ob1[c0 + 3]);
    }
    __syncthreads();

    if (tid < 64) {
        float s = out_b2[0];
        const float* t = s_t + tid * 132;
#pragma unroll 8
        for (int k = 0; k < 128; k++) s = fmaf(t[k], s_ow2[k], s);
        out[row0 + tid] = s;
    }
}

// ---------------------------------------------------------------------------
extern "C" void kernel_launch(void* const* d_in, const int* in_sizes, int n_in,
                              void* d_out, int out_size)
{
    // Two possible input orderings:
    //  A) setup_inputs() dict order:  delay, feat, PO_feat, pred, is_po, then weights
    //  B) reference() signature order: delay, feat, PO_feat, weights..., pred, is_po
    // Disambiguate via in_sizes[3]: pred slice = 15*32768*8 = 3,932,160 (A) vs
    // pi_w1 = 64 (B).
    int idx_pred, idx_ispo, wbase;
    if (in_sizes[3] == (LL - 1) * PP * KK) {   // dict order
        idx_pred = 3; idx_ispo = 4; wbase = 5;
    } else {                                    // signature order
        idx_pred = 23; idx_ispo = 24; wbase = 3;
    }

    const float* delay  = (const float*)d_in[0];
    const float* feat   = (const float*)d_in[1];
    const float* PO     = (const float*)d_in[2];
    const int*   pred   = (const int*)d_in[idx_pred];
    const int*   is_po  = (const int*)d_in[idx_ispo];
    const float* pi_w1  = (const float*)d_in[wbase + 0];
    const float* pi_b1  = (const float*)d_in[wbase + 1];
    const float* pi_w2  = (const float*)d_in[wbase + 2];
    const float* pi_b2  = (const float*)d_in[wbase + 3];
    const float* ne_w1  = (const float*)d_in[wbase + 4];
    const float* ne_b1  = (const float*)d_in[wbase + 5];
    const float* ne_w2  = (const float*)d_in[wbase + 6];
    const float* ne_b2  = (const float*)d_in[wbase + 7];
    const float* sf_w1  = (const float*)d_in[wbase + 8];
    const float* sf_b1  = (const float*)d_in[wbase + 9];
    const float* sf_w2  = (const float*)d_in[wbase + 10];
    const float* sf_b2  = (const float*)d_in[wbase + 11];
    const float* gl_w1  = (const float*)d_in[wbase + 12];
    const float* gl_b1  = (const float*)d_in[wbase + 13];
    const float* gl_w2  = (const float*)d_in[wbase + 14];
    const float* gl_b2  = (const float*)d_in[wbase + 15];
    const float* out_w1 = (const float*)d_in[wbase + 16];
    const float* out_b1 = (const float*)d_in[wbase + 17];
    const float* out_w2 = (const float*)d_in[wbase + 18];
    const float* out_b2 = (const float*)d_in[wbase + 19];
    float* out = (float*)d_out;

    const int grid = PP / NROWS;  // 512
    const size_t sh_init  = (size_t)(64 * 64 + 64 * 128 + 128) * 4;
    const size_t sh_layer = (size_t)(8192 + 8192 + 2048 + 16384 + 2048 + 128 + 128) * 4
                          + (size_t)(512 + 64) * 4;
    const size_t sh_final = (size_t)(16384 + 8192 + 8448 + 4096 + 128 + 128 + 128) * 4;

    cudaFuncSetAttribute(k_init,  cudaFuncAttributeMaxDynamicSharedMemorySize, (int)sh_init);
    cudaFuncSetAttribute(k_layer, cudaFuncAttributeMaxDynamicSharedMemorySize, (int)sh_layer);
    cudaFuncSetAttribute(k_final, cudaFuncAttributeMaxDynamicSharedMemorySize, (int)sh_final);

    k_init<<<grid, NTHREADS, sh_init>>>(delay, pi_w1, pi_b1, pi_w2, pi_b2);
    for (int i = 1; i < LL; i++) {
        k_layer<<<grid, NTHREADS, sh_layer>>>(i * PP,
            pred + (long long)(i - 1) * PP * KK,
            feat, ne_w1, ne_b1, ne_w2, ne_b2,
            sf_w1, sf_b1, sf_w2, sf_b2, is_po);
    }
    k_final<<<grid, NTHREADS, sh_final>>>(PO, gl_w1, gl_b1, gl_w2, gl_b2,
                                          out_w1, out_b1, out_w2, out_b2, out);
}